// round 6
// baseline (speedup 1.0000x reference)
#include <cuda_runtime.h>
#include <math.h>

#define NN 50000
#define FF 16
#define TT 12
#define HH 64
#define EE 1600000
#define KK 80      // F + H
#define FT 192     // F * T

// ---------------- scratch (device globals; no allocation allowed) ----------------
__device__ float g_deg[NN];
__device__ float g_dis[NN];
__device__ float g_self[NN];
__device__ int   g_rowptr[NN + 1];
__device__ int   g_cursor[NN];
__device__ int   g_esrc[EE];
__device__ float g_ewn[EE];
__device__ float g_AX[(size_t)NN * FT];    // A_hat @ x  (layout [n][f][t], same as x)
__device__ float g_AH[(size_t)NN * HH];    // A_hat @ h
__device__ float g_ARH[(size_t)NN * HH];   // A_hat @ (r*h)
__device__ float g_Z[(size_t)NN * HH];
__device__ float g_RH[(size_t)NN * HH];    // r * h
__device__ float g_h0[(size_t)NN * HH];    // zeros
__device__ float g_hs[(size_t)TT * NN * HH];
__device__ float g_align[(size_t)NN * TT];

// ---------------- preprocessing ----------------
__global__ void init_kernel() {
    int i = blockIdx.x * blockDim.x + threadIdx.x;
    if (i < NN) { g_deg[i] = 0.f; g_cursor[i] = 0; }
    if (i < NN * HH) g_h0[i] = 0.f;
}

__global__ void hist_kernel(const int* __restrict__ ei, const float* __restrict__ ew, int E) {
    int e = blockIdx.x * blockDim.x + threadIdx.x;
    if (e < E) {
        int d = ei[E + e];
        atomicAdd(&g_cursor[d], 1);
        atomicAdd(&g_deg[d], ew[e]);
    }
}

__global__ void dis_kernel() {
    int i = blockIdx.x * blockDim.x + threadIdx.x;
    if (i < NN) {
        float ds = rsqrtf(g_deg[i] + 1.0f);
        g_dis[i] = ds;
        g_self[i] = ds * ds;
    }
}

// single-block exclusive scan of counts (g_cursor) -> g_rowptr
__global__ void scan_kernel() {
    __shared__ int wsum[32];
    __shared__ int carry_s;
    int tid = threadIdx.x, lane = tid & 31, wid = tid >> 5;
    if (tid == 0) { carry_s = 0; g_rowptr[0] = 0; }
    __syncthreads();
    for (int base = 0; base < NN; base += 1024) {
        int i = base + tid;
        int v = (i < NN) ? g_cursor[i] : 0;
        int s = v;
        #pragma unroll
        for (int off = 1; off < 32; off <<= 1) {
            int t = __shfl_up_sync(0xffffffffu, s, off);
            if (lane >= off) s += t;
        }
        if (lane == 31) wsum[wid] = s;
        __syncthreads();
        if (wid == 0) {
            int ws = wsum[lane];
            #pragma unroll
            for (int off = 1; off < 32; off <<= 1) {
                int t = __shfl_up_sync(0xffffffffu, ws, off);
                if (lane >= off) ws += t;
            }
            wsum[lane] = ws;
        }
        __syncthreads();
        int add = ((wid > 0) ? wsum[wid - 1] : 0) + carry_s;
        int inc = s + add;
        if (i < NN) g_rowptr[i + 1] = inc;
        __syncthreads();
        if (tid == 1023) carry_s = carry_s + wsum[31];
        __syncthreads();
    }
}

__global__ void cursor_kernel() {
    int i = blockIdx.x * blockDim.x + threadIdx.x;
    if (i < NN) g_cursor[i] = g_rowptr[i];
}

__global__ void scatter_kernel(const int* __restrict__ ei, const float* __restrict__ ew, int E) {
    int e = blockIdx.x * blockDim.x + threadIdx.x;
    if (e < E) {
        int s = ei[e];
        int d = ei[E + e];
        int pos = atomicAdd(&g_cursor[d], 1);
        g_esrc[pos] = s;
        g_ewn[pos] = g_dis[s] * ew[e] * g_dis[d];
    }
}

// ---------------- CSR SpMM: out[n] = self[n]*feat[n] + sum_e ewn*feat[src] ----------------
// warp per node; lanes split into 2 halves over the edge range; 16 lanes x float4 = 64 cols/chunk
template <int NCH>
__device__ __forceinline__ void spmm_core(const float* __restrict__ feat, float* __restrict__ out) {
    const int C = NCH * 64;
    int gw = (blockIdx.x * blockDim.x + threadIdx.x) >> 5;
    if (gw >= NN) return;
    int lane = threadIdx.x & 31;
    int half = lane >> 4;
    int cl = lane & 15;
    int n = gw;
    int rs = g_rowptr[n], re = g_rowptr[n + 1];
    int cnt = re - rs;
    int c0 = (cnt + 1) >> 1;
    int start = rs + half * c0;
    int myCnt = half ? (cnt - c0) : c0;

    float4 acc[NCH];
    #pragma unroll
    for (int c = 0; c < NCH; c++) acc[c] = make_float4(0.f, 0.f, 0.f, 0.f);

    if (half == 0) {
        float sn = g_self[n];
        #pragma unroll
        for (int c = 0; c < NCH; c++) {
            float4 v = *(const float4*)&feat[(size_t)n * C + c * 64 + cl * 4];
            acc[c].x = sn * v.x; acc[c].y = sn * v.y; acc[c].z = sn * v.z; acc[c].w = sn * v.w;
        }
    }

    int iters = (c0 + 15) >> 4;
    for (int it = 0; it < iters; it++) {
        int base = it * 16;
        int s = 0; float w = 0.f;
        if (base + cl < myCnt) {
            int e = start + base + cl;
            s = g_esrc[e];
            w = g_ewn[e];
        }
        #pragma unroll
        for (int j = 0; j < 16; j++) {
            int sj = __shfl_sync(0xffffffffu, s, (lane & 16) + j);
            float wj = __shfl_sync(0xffffffffu, w, (lane & 16) + j);
            if (wj != 0.f) {
                const float* fr = feat + (size_t)sj * C;
                #pragma unroll
                for (int c = 0; c < NCH; c++) {
                    float4 v = *(const float4*)&fr[c * 64 + cl * 4];
                    acc[c].x += wj * v.x; acc[c].y += wj * v.y;
                    acc[c].z += wj * v.z; acc[c].w += wj * v.w;
                }
            }
        }
    }
    // combine halves
    #pragma unroll
    for (int c = 0; c < NCH; c++) {
        acc[c].x += __shfl_xor_sync(0xffffffffu, acc[c].x, 16);
        acc[c].y += __shfl_xor_sync(0xffffffffu, acc[c].y, 16);
        acc[c].z += __shfl_xor_sync(0xffffffffu, acc[c].z, 16);
        acc[c].w += __shfl_xor_sync(0xffffffffu, acc[c].w, 16);
    }
    if (half == 0) {
        #pragma unroll
        for (int c = 0; c < NCH; c++)
            *(float4*)&out[(size_t)n * C + c * 64 + cl * 4] = acc[c];
    }
}

__global__ void spmm_x_kernel(const float* __restrict__ x) { spmm_core<3>(x, g_AX); }
__global__ void spmm_h_kernel(int t) { spmm_core<1>(g_hs + (size_t)(t - 1) * NN * HH, g_AH); }
__global__ void spmm_rh_kernel() { spmm_core<1>(g_RH, g_ARH); }

__device__ __forceinline__ float sigm(float x) { return 1.0f / (1.0f + __expf(-x)); }

// ---------------- GEMM z/r: [AX_t | AH] (N x 80) @ [Wz | Wr] (80 x 128) ----------------
// tile 64 rows x 128 cols, 256 threads, 4x8 micro-tile; epilogue: Z=sigmoid, RH=sigmoid(r)*h
#define ZR_SMEM ((KK * 68 + KK * 128) * 4)
__global__ __launch_bounds__(256) void gemm_zr_kernel(
    int t, const float* __restrict__ Wz, const float* __restrict__ bz,
    const float* __restrict__ Wr, const float* __restrict__ br_) {
    extern __shared__ float sm[];
    float* As = sm;            // [80][68]
    float* Bs = sm + KK * 68;  // [80][128]
    const float* AH = (t == 0) ? g_h0 : g_AH;
    const float* hprev = (t == 0) ? g_h0 : (g_hs + (size_t)(t - 1) * NN * HH);
    int tid = threadIdx.x;
    int block_row = blockIdx.x * 64;

    for (int i = tid; i < 64 * KK; i += 256) {
        int r = i / KK, k = i % KK;
        int row = block_row + r;
        float v = 0.f;
        if (row < NN)
            v = (k < FF) ? g_AX[(size_t)row * FT + k * TT + t]
                         : AH[(size_t)row * HH + (k - FF)];
        As[k * 68 + r] = v;
    }
    for (int i = tid; i < KK * 128; i += 256) {
        int k = i >> 7, j = i & 127;
        Bs[i] = (j < HH) ? Wz[k * HH + j] : Wr[k * HH + (j - HH)];
    }
    __syncthreads();

    int tc = tid & 15, tr = tid >> 4;
    float acc[4][8];
    #pragma unroll
    for (int rr = 0; rr < 4; rr++)
        #pragma unroll
        for (int cc = 0; cc < 8; cc++) acc[rr][cc] = 0.f;

    #pragma unroll 8
    for (int k = 0; k < KK; k++) {
        float4 a = *(float4*)&As[k * 68 + tr * 4];
        float4 b0 = *(float4*)&Bs[k * 128 + tc * 8];
        float4 b1 = *(float4*)&Bs[k * 128 + tc * 8 + 4];
        float av[4] = {a.x, a.y, a.z, a.w};
        float bv[8] = {b0.x, b0.y, b0.z, b0.w, b1.x, b1.y, b1.z, b1.w};
        #pragma unroll
        for (int rr = 0; rr < 4; rr++)
            #pragma unroll
            for (int cc = 0; cc < 8; cc++)
                acc[rr][cc] += av[rr] * bv[cc];
    }

    #pragma unroll
    for (int rr = 0; rr < 4; rr++) {
        int row = block_row + tr * 4 + rr;
        if (row < NN) {
            #pragma unroll
            for (int cc = 0; cc < 8; cc++) {
                int j = tc * 8 + cc;
                float v = acc[rr][cc];
                if (j < HH) {
                    g_Z[(size_t)row * HH + j] = sigm(v + bz[j]);
                } else {
                    int jj = j - HH;
                    float rv = sigm(v + br_[jj]);
                    g_RH[(size_t)row * HH + jj] = rv * hprev[(size_t)row * HH + jj];
                }
            }
        }
    }
}

// ---------------- GEMM h: [AX_t | ARH] @ Wh; epilogue GRU update -> hs[t] ----------------
__global__ __launch_bounds__(256) void gemm_h_kernel(
    int t, const float* __restrict__ Wh, const float* __restrict__ bh) {
    __shared__ float As[KK * 68];
    __shared__ float Bs[KK * HH];
    const float* ARH = (t == 0) ? g_h0 : g_ARH;
    const float* hprev = (t == 0) ? g_h0 : (g_hs + (size_t)(t - 1) * NN * HH);
    float* hout = g_hs + (size_t)t * NN * HH;
    int tid = threadIdx.x;
    int block_row = blockIdx.x * 64;

    for (int i = tid; i < 64 * KK; i += 256) {
        int r = i / KK, k = i % KK;
        int row = block_row + r;
        float v = 0.f;
        if (row < NN)
            v = (k < FF) ? g_AX[(size_t)row * FT + k * TT + t]
                         : ARH[(size_t)row * HH + (k - FF)];
        As[k * 68 + r] = v;
    }
    for (int i = tid; i < KK * HH; i += 256) Bs[i] = Wh[i];
    __syncthreads();

    int tc = tid & 15, tr = tid >> 4;
    float acc[4][4];
    #pragma unroll
    for (int rr = 0; rr < 4; rr++)
        #pragma unroll
        for (int cc = 0; cc < 4; cc++) acc[rr][cc] = 0.f;

    #pragma unroll 8
    for (int k = 0; k < KK; k++) {
        float4 a = *(float4*)&As[k * 68 + tr * 4];
        float4 b = *(float4*)&Bs[k * HH + tc * 4];
        float av[4] = {a.x, a.y, a.z, a.w};
        float bv[4] = {b.x, b.y, b.z, b.w};
        #pragma unroll
        for (int rr = 0; rr < 4; rr++)
            #pragma unroll
            for (int cc = 0; cc < 4; cc++)
                acc[rr][cc] += av[rr] * bv[cc];
    }

    #pragma unroll
    for (int rr = 0; rr < 4; rr++) {
        int row = block_row + tr * 4 + rr;
        if (row < NN) {
            #pragma unroll
            for (int cc = 0; cc < 4; cc++) {
                int j = tc * 4 + cc;
                float hc = tanhf(acc[rr][cc] + bh[j]);
                float z = g_Z[(size_t)row * HH + j];
                float hp = hprev[(size_t)row * HH + j];
                hout[(size_t)row * HH + j] = z * hp + (1.f - z) * hc;
            }
        }
    }
}

// ---------------- attention score: align[n][t] = sum_j tanh(hs[n,t]@Wa + ba)_j * cv_j ----------------
// rows are flat (t*N + n) over g_hs; 64x64 tile GEMM + in-epilogue row reduction
__global__ __launch_bounds__(256) void attn_score_kernel(
    const float* __restrict__ Wa, const float* __restrict__ ba, const float* __restrict__ cv) {
    __shared__ float As[HH * 68];
    __shared__ float Bs[HH * HH];
    __shared__ float ba_s[HH], cv_s[HH];
    const int TN = TT * NN;
    int tid = threadIdx.x;
    int block_row = blockIdx.x * 64;

    for (int i = tid; i < 64 * HH; i += 256) {
        int r = i >> 6, k = i & 63;
        int row = block_row + r;
        As[k * 68 + r] = (row < TN) ? g_hs[(size_t)row * HH + k] : 0.f;
    }
    for (int i = tid; i < HH * HH; i += 256) Bs[i] = Wa[i];
    if (tid < HH) { ba_s[tid] = ba[tid]; cv_s[tid] = cv[tid]; }
    __syncthreads();

    int tc = tid & 15, tr = tid >> 4;
    float acc[4][4];
    #pragma unroll
    for (int rr = 0; rr < 4; rr++)
        #pragma unroll
        for (int cc = 0; cc < 4; cc++) acc[rr][cc] = 0.f;

    #pragma unroll 8
    for (int k = 0; k < HH; k++) {
        float4 a = *(float4*)&As[k * 68 + tr * 4];
        float4 b = *(float4*)&Bs[k * HH + tc * 4];
        float av[4] = {a.x, a.y, a.z, a.w};
        float bv[4] = {b.x, b.y, b.z, b.w};
        #pragma unroll
        for (int rr = 0; rr < 4; rr++)
            #pragma unroll
            for (int cc = 0; cc < 4; cc++)
                acc[rr][cc] += av[rr] * bv[cc];
    }

    #pragma unroll
    for (int rr = 0; rr < 4; rr++) {
        float p = 0.f;
        #pragma unroll
        for (int cc = 0; cc < 4; cc++) {
            int j = tc * 4 + cc;
            p += tanhf(acc[rr][cc] + ba_s[j]) * cv_s[j];
        }
        #pragma unroll
        for (int off = 1; off < 16; off <<= 1)
            p += __shfl_xor_sync(0xffffffffu, p, off);
        int row = block_row + tr * 4 + rr;
        if (tc == 0 && row < TN) {
            int t = row / NN;
            int n = row % NN;
            g_align[(size_t)n * TT + t] = p;
        }
    }
}

// ---------------- softmax over T + context + FC ----------------
__global__ __launch_bounds__(256) void attn_out_kernel(
    const float* __restrict__ Wfc, const float* __restrict__ bfc, float* __restrict__ out) {
    __shared__ float wf_s[HH];
    __shared__ float red[4][2];
    int tid = threadIdx.x;
    int g = tid >> 6, j = tid & 63;
    int n = blockIdx.x * 4 + g;
    if (tid < HH) wf_s[tid] = Wfc[tid];
    __syncthreads();
    if (n >= NN) return;

    float a[TT];
    float m = -1e30f;
    #pragma unroll
    for (int t = 0; t < TT; t++) { a[t] = g_align[(size_t)n * TT + t]; m = fmaxf(m, a[t]); }
    float se = 0.f;
    #pragma unroll
    for (int t = 0; t < TT; t++) { a[t] = __expf(a[t] - m); se += a[t]; }
    float inv = 1.f / se;
    float ctx = 0.f;
    #pragma unroll
    for (int t = 0; t < TT; t++)
        ctx += a[t] * g_hs[(size_t)t * NN * HH + (size_t)n * HH + j];
    ctx *= inv;

    float p = ctx * wf_s[j];
    #pragma unroll
    for (int off = 16; off > 0; off >>= 1)
        p += __shfl_xor_sync(0xffffffffu, p, off);
    int lane = tid & 31;
    if (lane == 0) red[g][j >> 5] = p;
    __syncthreads();
    if (j == 0) out[n] = red[g][0] + red[g][1] + bfc[0];
}

// ---------------- launch ----------------
extern "C" void kernel_launch(void* const* d_in, const int* in_sizes, int n_in,
                              void* d_out, int out_size) {
    const float* x   = (const float*)d_in[0];
    const int*   ei  = (const int*)d_in[1];
    const float* ew  = (const float*)d_in[2];
    const float* Wz  = (const float*)d_in[3];
    const float* bz  = (const float*)d_in[4];
    const float* Wr  = (const float*)d_in[5];
    const float* br_ = (const float*)d_in[6];
    const float* Wh  = (const float*)d_in[7];
    const float* bh  = (const float*)d_in[8];
    const float* Wa  = (const float*)d_in[9];
    const float* ba  = (const float*)d_in[10];
    const float* cv  = (const float*)d_in[11];
    const float* Wfc = (const float*)d_in[12];
    const float* bfc = (const float*)d_in[13];
    float* out = (float*)d_out;
    int E = in_sizes[2];

    cudaFuncSetAttribute(gemm_zr_kernel, cudaFuncAttributeMaxDynamicSharedMemorySize, ZR_SMEM);

    init_kernel<<<(NN * HH + 255) / 256, 256>>>();
    hist_kernel<<<(E + 255) / 256, 256>>>(ei, ew, E);
    dis_kernel<<<(NN + 255) / 256, 256>>>();
    scan_kernel<<<1, 1024>>>();
    cursor_kernel<<<(NN + 255) / 256, 256>>>();
    scatter_kernel<<<(E + 255) / 256, 256>>>(ei, ew, E);

    spmm_x_kernel<<<(NN + 7) / 8, 256>>>(x);

    int gemm_blocks = (NN + 63) / 64;
    int spmm_blocks = (NN + 7) / 8;
    for (int t = 0; t < TT; t++) {
        if (t > 0) spmm_h_kernel<<<spmm_blocks, 256>>>(t);
        gemm_zr_kernel<<<gemm_blocks, 256, ZR_SMEM>>>(t, Wz, bz, Wr, br_);
        if (t > 0) spmm_rh_kernel<<<spmm_blocks, 256>>>();
        gemm_h_kernel<<<gemm_blocks, 256>>>(t, Wh, bh);
    }

    attn_score_kernel<<<(TT * NN + 63) / 64, 256>>>(Wa, ba, cv);
    attn_out_kernel<<<(NN + 3) / 4, 256>>>(Wfc, bfc, out);
}

// round 11
// speedup vs baseline: 1.0165x; 1.0165x over previous
#include <cuda_runtime.h>
#include <cuda_fp16.h>
#include <math.h>

#define NN 50000
#define FF 16
#define TT 12
#define HH 64
#define EE 1600000
#define KK 80      // F + H
#define FT 192     // F * T

// ---------------- scratch (device globals; no allocation allowed) ----------------
__device__ float g_deg[NN];
__device__ float g_dis[NN];
__device__ float g_self[NN];
__device__ int   g_rowptr[NN + 1];
__device__ int   g_cursor[NN];
__device__ int   g_esrc[EE];
__device__ float g_ewn[EE];
__device__ float g_AX[(size_t)NN * FT];    // A_hat @ x  (fp32, layout [n][f*T+t])
__device__ float g_AH[(size_t)NN * HH];    // A_hat @ h
__device__ float g_ARH[(size_t)NN * HH];   // A_hat @ (r*h)
__device__ float g_Z[(size_t)NN * HH];
__device__ float g_h0[(size_t)NN * HH];    // zeros (static zero-init, never written)
__device__ float g_hs[(size_t)TT * NN * HH];
__device__ float g_align[(size_t)NN * TT];

// fp16 gather tables (SpMM inputs)
__device__ __half g_xh[(size_t)NN * FT];   // x in half
__device__ __half g_hh[(size_t)NN * HH];   // h_{t-1} in half
__device__ __half g_RHh[(size_t)NN * HH];  // r*h in half

// ---------------- preprocessing ----------------
__global__ void init_kernel() {
    int i = blockIdx.x * blockDim.x + threadIdx.x;
    if (i < NN) { g_deg[i] = 0.f; g_cursor[i] = 0; }
}

__global__ void tohalf_kernel(const float* __restrict__ x) {
    int i = blockIdx.x * blockDim.x + threadIdx.x;
    if (i < NN * FT / 2) {
        float2 v = ((const float2*)x)[i];
        ((__half2*)g_xh)[i] = __floats2half2_rn(v.x, v.y);
    }
}

__global__ void hist_kernel(const int* __restrict__ ei, const float* __restrict__ ew, int E) {
    int e = blockIdx.x * blockDim.x + threadIdx.x;
    if (e < E) {
        int d = ei[E + e];
        atomicAdd(&g_cursor[d], 1);
        atomicAdd(&g_deg[d], ew[e]);
    }
}

// chunked exclusive scan of counts -> rowptr (+ cursor init + dis/self), 1 block
__global__ __launch_bounds__(1024) void scan_kernel() {
    const int CH = (NN + 1023) / 1024;
    int tid = threadIdx.x, lane = tid & 31, wid = tid >> 5;
    int start = tid * CH;
    int end = min(start + CH, NN);
    int sum = 0;
    for (int i = start; i < end; i++) sum += g_cursor[i];

    __shared__ int wsum[32];
    int s = sum;
    #pragma unroll
    for (int off = 1; off < 32; off <<= 1) {
        int t = __shfl_up_sync(0xffffffffu, s, off);
        if (lane >= off) s += t;
    }
    if (lane == 31) wsum[wid] = s;
    __syncthreads();
    if (wid == 0) {
        int ws = wsum[lane];
        #pragma unroll
        for (int off = 1; off < 32; off <<= 1) {
            int t = __shfl_up_sync(0xffffffffu, ws, off);
            if (lane >= off) ws += t;
        }
        wsum[lane] = ws;
    }
    __syncthreads();
    int excl = (s - sum) + ((wid > 0) ? wsum[wid - 1] : 0);

    int run = excl;
    for (int i = start; i < end; i++) {
        int c = g_cursor[i];
        g_rowptr[i] = run;
        g_cursor[i] = run;
        float ds = rsqrtf(g_deg[i] + 1.0f);
        g_dis[i] = ds;
        g_self[i] = ds * ds;
        run += c;
    }
    if (tid == 1023) g_rowptr[NN] = excl + sum;
}

__global__ void scatter_kernel(const int* __restrict__ ei, const float* __restrict__ ew, int E) {
    int e = blockIdx.x * blockDim.x + threadIdx.x;
    if (e < E) {
        int s = ei[e];
        int d = ei[E + e];
        int pos = atomicAdd(&g_cursor[d], 1);
        g_esrc[pos] = s;
        g_ewn[pos] = g_dis[s] * ew[e] * g_dis[d];
    }
}

// ---------------- CSR SpMM (fp16 feat, fp32 accum) ----------------
// warp per node; 2 halves over the edge range; 16 lanes x 4 halves (8B) = 64 cols/chunk
template <int NCH>
__device__ __forceinline__ void spmm16(const __half* __restrict__ feat, float* __restrict__ out) {
    const int C = NCH * 64;
    int gw = (blockIdx.x * blockDim.x + threadIdx.x) >> 5;
    if (gw >= NN) return;
    int lane = threadIdx.x & 31;
    int half = lane >> 4;
    int cl = lane & 15;
    int n = gw;
    int rs = g_rowptr[n], re = g_rowptr[n + 1];
    int cnt = re - rs;
    int c0 = (cnt + 1) >> 1;
    int start = rs + half * c0;
    int myCnt = half ? (cnt - c0) : c0;

    float4 acc[NCH];
    #pragma unroll
    for (int c = 0; c < NCH; c++) acc[c] = make_float4(0.f, 0.f, 0.f, 0.f);

    if (half == 0) {
        float sn = g_self[n];
        const __half* fr = feat + (size_t)n * C;
        #pragma unroll
        for (int c = 0; c < NCH; c++) {
            uint2 v = *(const uint2*)&fr[c * 64 + cl * 4];
            float2 f0 = __half22float2(*reinterpret_cast<__half2*>(&v.x));
            float2 f1 = __half22float2(*reinterpret_cast<__half2*>(&v.y));
            acc[c].x = sn * f0.x; acc[c].y = sn * f0.y;
            acc[c].z = sn * f1.x; acc[c].w = sn * f1.y;
        }
    }

    int iters = (c0 + 15) >> 4;
    for (int it = 0; it < iters; it++) {
        int base = it * 16;
        int s = 0; float w = 0.f;
        if (base + cl < myCnt) {
            int e = start + base + cl;
            s = g_esrc[e];
            w = g_ewn[e];
        }
        #pragma unroll
        for (int j = 0; j < 16; j++) {
            int sj = __shfl_sync(0xffffffffu, s, (lane & 16) + j);
            float wj = __shfl_sync(0xffffffffu, w, (lane & 16) + j);
            if (wj != 0.f) {
                const __half* fr = feat + (size_t)sj * C;
                #pragma unroll
                for (int c = 0; c < NCH; c++) {
                    uint2 v = *(const uint2*)&fr[c * 64 + cl * 4];
                    float2 f0 = __half22float2(*reinterpret_cast<__half2*>(&v.x));
                    float2 f1 = __half22float2(*reinterpret_cast<__half2*>(&v.y));
                    acc[c].x += wj * f0.x; acc[c].y += wj * f0.y;
                    acc[c].z += wj * f1.x; acc[c].w += wj * f1.y;
                }
            }
        }
    }
    #pragma unroll
    for (int c = 0; c < NCH; c++) {
        acc[c].x += __shfl_xor_sync(0xffffffffu, acc[c].x, 16);
        acc[c].y += __shfl_xor_sync(0xffffffffu, acc[c].y, 16);
        acc[c].z += __shfl_xor_sync(0xffffffffu, acc[c].z, 16);
        acc[c].w += __shfl_xor_sync(0xffffffffu, acc[c].w, 16);
    }
    if (half == 0) {
        #pragma unroll
        for (int c = 0; c < NCH; c++)
            *(float4*)&out[(size_t)n * C + c * 64 + cl * 4] = acc[c];
    }
}

__global__ void spmm_x_kernel()  { spmm16<3>(g_xh, g_AX); }
__global__ void spmm_h_kernel()  { spmm16<1>(g_hh, g_AH); }
__global__ void spmm_rh_kernel() { spmm16<1>(g_RHh, g_ARH); }

__device__ __forceinline__ float sigm(float x) { return 1.0f / (1.0f + __expf(-x)); }

// ---------------- GEMM z/r: [AX_t | AH] (N x 80) @ [Wz | Wr] (80 x 128) ----------------
#define ZR_SMEM ((KK * 68 + KK * 128) * 4)
__global__ __launch_bounds__(256) void gemm_zr_kernel(
    int t, const float* __restrict__ Wz, const float* __restrict__ bz,
    const float* __restrict__ Wr, const float* __restrict__ br_) {
    extern __shared__ float sm[];
    float* As = sm;            // [80][68]
    float* Bs = sm + KK * 68;  // [80][128]
    const float* AH = (t == 0) ? g_h0 : g_AH;
    const float* hprev = (t == 0) ? g_h0 : (g_hs + (size_t)(t - 1) * NN * HH);
    int tid = threadIdx.x;
    int block_row = blockIdx.x * 64;

    for (int i = tid; i < 64 * KK; i += 256) {
        int r = i / KK, k = i % KK;
        int row = block_row + r;
        float v = 0.f;
        if (row < NN)
            v = (k < FF) ? g_AX[(size_t)row * FT + k * TT + t]
                         : AH[(size_t)row * HH + (k - FF)];
        As[k * 68 + r] = v;
    }
    for (int i = tid; i < KK * 128; i += 256) {
        int k = i >> 7, j = i & 127;
        Bs[i] = (j < HH) ? Wz[k * HH + j] : Wr[k * HH + (j - HH)];
    }
    __syncthreads();

    int tc = tid & 15, tr = tid >> 4;
    float acc[4][8];
    #pragma unroll
    for (int rr = 0; rr < 4; rr++)
        #pragma unroll
        for (int cc = 0; cc < 8; cc++) acc[rr][cc] = 0.f;

    #pragma unroll 8
    for (int k = 0; k < KK; k++) {
        float4 a = *(float4*)&As[k * 68 + tr * 4];
        float4 b0 = *(float4*)&Bs[k * 128 + tc * 8];
        float4 b1 = *(float4*)&Bs[k * 128 + tc * 8 + 4];
        float av[4] = {a.x, a.y, a.z, a.w};
        float bv[8] = {b0.x, b0.y, b0.z, b0.w, b1.x, b1.y, b1.z, b1.w};
        #pragma unroll
        for (int rr = 0; rr < 4; rr++)
            #pragma unroll
            for (int cc = 0; cc < 8; cc++)
                acc[rr][cc] += av[rr] * bv[cc];
    }

    #pragma unroll
    for (int rr = 0; rr < 4; rr++) {
        int row = block_row + tr * 4 + rr;
        if (row < NN) {
            #pragma unroll
            for (int cc = 0; cc < 8; cc++) {
                int j = tc * 8 + cc;
                float v = acc[rr][cc];
                if (j < HH) {
                    g_Z[(size_t)row * HH + j] = sigm(v + bz[j]);
                } else {
                    int jj = j - HH;
                    float rv = sigm(v + br_[jj]);
                    g_RHh[(size_t)row * HH + jj] =
                        __float2half_rn(rv * hprev[(size_t)row * HH + jj]);
                }
            }
        }
    }
}

// ---------------- GEMM h: [AX_t | ARH] @ Wh; epilogue GRU update -> hs[t], hh ----------------
__global__ __launch_bounds__(256) void gemm_h_kernel(
    int t, const float* __restrict__ Wh, const float* __restrict__ bh) {
    __shared__ float As[KK * 68];
    __shared__ float Bs[KK * HH];
    const float* ARH = (t == 0) ? g_h0 : g_ARH;
    const float* hprev = (t == 0) ? g_h0 : (g_hs + (size_t)(t - 1) * NN * HH);
    float* hout = g_hs + (size_t)t * NN * HH;
    int tid = threadIdx.x;
    int block_row = blockIdx.x * 64;

    for (int i = tid; i < 64 * KK; i += 256) {
        int r = i / KK, k = i % KK;
        int row = block_row + r;
        float v = 0.f;
        if (row < NN)
            v = (k < FF) ? g_AX[(size_t)row * FT + k * TT + t]
                         : ARH[(size_t)row * HH + (k - FF)];
        As[k * 68 + r] = v;
    }
    for (int i = tid; i < KK * HH; i += 256) Bs[i] = Wh[i];
    __syncthreads();

    int tc = tid & 15, tr = tid >> 4;
    float acc[4][4];
    #pragma unroll
    for (int rr = 0; rr < 4; rr++)
        #pragma unroll
        for (int cc = 0; cc < 4; cc++) acc[rr][cc] = 0.f;

    #pragma unroll 8
    for (int k = 0; k < KK; k++) {
        float4 a = *(float4*)&As[k * 68 + tr * 4];
        float4 b = *(float4*)&Bs[k * HH + tc * 4];
        float av[4] = {a.x, a.y, a.z, a.w};
        float bv[4] = {b.x, b.y, b.z, b.w};
        #pragma unroll
        for (int rr = 0; rr < 4; rr++)
            #pragma unroll
            for (int cc = 0; cc < 4; cc++)
                acc[rr][cc] += av[rr] * bv[cc];
    }

    #pragma unroll
    for (int rr = 0; rr < 4; rr++) {
        int row = block_row + tr * 4 + rr;
        if (row < NN) {
            #pragma unroll
            for (int cc = 0; cc < 4; cc++) {
                int j = tc * 4 + cc;
                float hc = tanhf(acc[rr][cc] + bh[j]);
                float z = g_Z[(size_t)row * HH + j];
                float hp = hprev[(size_t)row * HH + j];
                float hn = z * hp + (1.f - z) * hc;
                hout[(size_t)row * HH + j] = hn;
                g_hh[(size_t)row * HH + j] = __float2half_rn(hn);
            }
        }
    }
}

// ---------------- attention score ----------------
__global__ __launch_bounds__(256) void attn_score_kernel(
    const float* __restrict__ Wa, const float* __restrict__ ba, const float* __restrict__ cv) {
    __shared__ float As[HH * 68];
    __shared__ float Bs[HH * HH];
    __shared__ float ba_s[HH], cv_s[HH];
    const int TN = TT * NN;
    int tid = threadIdx.x;
    int block_row = blockIdx.x * 64;

    for (int i = tid; i < 64 * HH; i += 256) {
        int r = i >> 6, k = i & 63;
        int row = block_row + r;
        As[k * 68 + r] = (row < TN) ? g_hs[(size_t)row * HH + k] : 0.f;
    }
    for (int i = tid; i < HH * HH; i += 256) Bs[i] = Wa[i];
    if (tid < HH) { ba_s[tid] = ba[tid]; cv_s[tid] = cv[tid]; }
    __syncthreads();

    int tc = tid & 15, tr = tid >> 4;
    float acc[4][4];
    #pragma unroll
    for (int rr = 0; rr < 4; rr++)
        #pragma unroll
        for (int cc = 0; cc < 4; cc++) acc[rr][cc] = 0.f;

    #pragma unroll 8
    for (int k = 0; k < HH; k++) {
        float4 a = *(float4*)&As[k * 68 + tr * 4];
        float4 b = *(float4*)&Bs[k * HH + tc * 4];
        float av[4] = {a.x, a.y, a.z, a.w};
        float bv[4] = {b.x, b.y, b.z, b.w};
        #pragma unroll
        for (int rr = 0; rr < 4; rr++)
            #pragma unroll
            for (int cc = 0; cc < 4; cc++)
                acc[rr][cc] += av[rr] * bv[cc];
    }

    #pragma unroll
    for (int rr = 0; rr < 4; rr++) {
        float p = 0.f;
        #pragma unroll
        for (int cc = 0; cc < 4; cc++) {
            int j = tc * 4 + cc;
            p += tanhf(acc[rr][cc] + ba_s[j]) * cv_s[j];
        }
        #pragma unroll
        for (int off = 1; off < 16; off <<= 1)
            p += __shfl_xor_sync(0xffffffffu, p, off);
        int row = block_row + tr * 4 + rr;
        if (tc == 0 && row < TN) {
            int t = row / NN;
            int n = row % NN;
            g_align[(size_t)n * TT + t] = p;
        }
    }
}

// ---------------- softmax over T + context + FC ----------------
__global__ __launch_bounds__(256) void attn_out_kernel(
    const float* __restrict__ Wfc, const float* __restrict__ bfc, float* __restrict__ out) {
    __shared__ float wf_s[HH];
    __shared__ float red[4][2];
    int tid = threadIdx.x;
    int g = tid >> 6, j = tid & 63;
    int n = blockIdx.x * 4 + g;
    if (tid < HH) wf_s[tid] = Wfc[tid];
    __syncthreads();
    if (n >= NN) return;

    float a[TT];
    float m = -1e30f;
    #pragma unroll
    for (int t = 0; t < TT; t++) { a[t] = g_align[(size_t)n * TT + t]; m = fmaxf(m, a[t]); }
    float se = 0.f;
    #pragma unroll
    for (int t = 0; t < TT; t++) { a[t] = __expf(a[t] - m); se += a[t]; }
    float inv = 1.f / se;
    float ctx = 0.f;
    #pragma unroll
    for (int t = 0; t < TT; t++)
        ctx += a[t] * g_hs[(size_t)t * NN * HH + (size_t)n * HH + j];
    ctx *= inv;

    float p = ctx * wf_s[j];
    #pragma unroll
    for (int off = 16; off > 0; off >>= 1)
        p += __shfl_xor_sync(0xffffffffu, p, off);
    int lane = tid & 31;
    if (lane == 0) red[g][j >> 5] = p;
    __syncthreads();
    if (j == 0) out[n] = red[g][0] + red[g][1] + bfc[0];
}

// ---------------- launch ----------------
extern "C" void kernel_launch(void* const* d_in, const int* in_sizes, int n_in,
                              void* d_out, int out_size) {
    const float* x   = (const float*)d_in[0];
    const int*   ei  = (const int*)d_in[1];
    const float* ew  = (const float*)d_in[2];
    const float* Wz  = (const float*)d_in[3];
    const float* bz  = (const float*)d_in[4];
    const float* Wr  = (const float*)d_in[5];
    const float* br_ = (const float*)d_in[6];
    const float* Wh  = (const float*)d_in[7];
    const float* bh  = (const float*)d_in[8];
    const float* Wa  = (const float*)d_in[9];
    const float* ba  = (const float*)d_in[10];
    const float* cv  = (const float*)d_in[11];
    const float* Wfc = (const float*)d_in[12];
    const float* bfc = (const float*)d_in[13];
    float* out = (float*)d_out;
    int E = in_sizes[2];

    cudaFuncSetAttribute(gemm_zr_kernel, cudaFuncAttributeMaxDynamicSharedMemorySize, ZR_SMEM);

    init_kernel<<<(NN + 255) / 256, 256>>>();
    tohalf_kernel<<<(NN * FT / 2 + 255) / 256, 256>>>(x);
    hist_kernel<<<(E + 255) / 256, 256>>>(ei, ew, E);
    scan_kernel<<<1, 1024>>>();
    scatter_kernel<<<(E + 255) / 256, 256>>>(ei, ew, E);

    int spmm_blocks = (NN + 7) / 8;
    spmm_x_kernel<<<spmm_blocks, 256>>>();

    int gemm_blocks = (NN + 63) / 64;
    for (int t = 0; t < TT; t++) {
        if (t > 0) spmm_h_kernel<<<spmm_blocks, 256>>>();
        gemm_zr_kernel<<<gemm_blocks, 256, ZR_SMEM>>>(t, Wz, bz, Wr, br_);
        if (t > 0) spmm_rh_kernel<<<spmm_blocks, 256>>>();
        gemm_h_kernel<<<gemm_blocks, 256>>>(t, Wh, bh);
    }

    attn_score_kernel<<<(TT * NN + 63) / 64, 256>>>(Wa, ba, cv);
    attn_out_kernel<<<(NN + 3) / 4, 256>>>(Wfc, bfc, out);
}

// round 14
// speedup vs baseline: 1.0459x; 1.0290x over previous
#include <cuda_runtime.h>
#include <cuda_fp16.h>
#include <math.h>

#define NN 50000
#define FF 16
#define TT 12
#define HH 64
#define EE 1600000
#define KK 80      // F + H
#define FT 192     // F * T
#define NTILES ((NN + 63) / 64)
#define SCAN_BLOCKS ((NN + 255) / 256)

// ---------------- scratch (device globals; zero-initialized) ----------------
__device__ float g_deg[NN];
__device__ float g_dis[NN];
__device__ float g_self[NN];
__device__ int   g_rowptr[NN + 1];
__device__ int   g_cursor[NN];
__device__ int   g_bsum[SCAN_BLOCKS];
__device__ int   g_boff[SCAN_BLOCKS];
__device__ int   g_esrc[EE];
__device__ float g_ewn[EE];
__device__ float g_AX[(size_t)NN * FT];    // A_hat @ x  (fp32, layout [n][f*T+t])
__device__ float g_Z[(size_t)NN * HH];
__device__ float g_h0[(size_t)NN * HH];    // zeros (never written)
__device__ float g_hs[(size_t)TT * NN * HH];
__device__ float g_align[(size_t)NN * TT];

// fp16 gather tables (SpMM inputs)
__device__ __half g_xh[(size_t)NN * FT];   // x in half
__device__ __half g_hh[(size_t)NN * HH];   // h_{t-1} in half
__device__ __half g_RHh[(size_t)NN * HH];  // r*h in half

__device__ __forceinline__ float sigm(float x) { return 1.0f / (1.0f + __expf(-x)); }
__device__ __forceinline__ float tanh_fast(float x) {
    float y; asm("tanh.approx.f32 %0, %1;" : "=f"(y) : "f"(x)); return y;
}

// ---------------- preprocessing ----------------
__global__ void init_kernel() {
    int i = blockIdx.x * blockDim.x + threadIdx.x;
    if (i < NN) { g_deg[i] = 0.f; g_cursor[i] = 0; }
}

__global__ void tohalf_kernel(const float* __restrict__ x) {
    int i = blockIdx.x * blockDim.x + threadIdx.x;
    if (i < NN * FT / 2) {
        float2 v = ((const float2*)x)[i];
        ((__half2*)g_xh)[i] = __floats2half2_rn(v.x, v.y);
    }
}

__global__ void hist_kernel(const int* __restrict__ ei, const float* __restrict__ ew, int E) {
    int e = blockIdx.x * blockDim.x + threadIdx.x;
    if (e < E) {
        int d = ei[E + e];
        atomicAdd(&g_cursor[d], 1);
        atomicAdd(&g_deg[d], ew[e]);
    }
}

// block exclusive scan helper: returns exclusive prefix of v within the block
__device__ __forceinline__ int block_exscan(int v, int tid) {
    __shared__ int wsum[8];
    int lane = tid & 31, wid = tid >> 5;
    int s = v;
    #pragma unroll
    for (int off = 1; off < 32; off <<= 1) {
        int t = __shfl_up_sync(0xffffffffu, s, off);
        if (lane >= off) s += t;
    }
    if (lane == 31) wsum[wid] = s;
    __syncthreads();
    if (wid == 0 && lane < 8) {
        int ws = wsum[lane];
        #pragma unroll
        for (int off = 1; off < 8; off <<= 1) {
            int t = __shfl_up_sync(0x000000ffu, ws, off);
            if (lane >= off) ws += t;
        }
        wsum[lane] = ws;
    }
    __syncthreads();
    return (s - v) + ((wid > 0) ? wsum[wid - 1] : 0);
}

__global__ __launch_bounds__(256) void scan_p1() {
    int i = blockIdx.x * 256 + threadIdx.x;
    int v = (i < NN) ? g_cursor[i] : 0;
    int ex = block_exscan(v, threadIdx.x);
    if (threadIdx.x == 255) g_bsum[blockIdx.x] = ex + v;
}

__global__ __launch_bounds__(256) void scan_p2() {
    int tid = threadIdx.x;
    int v = (tid < SCAN_BLOCKS) ? g_bsum[tid] : 0;
    int ex = block_exscan(v, tid);
    if (tid < SCAN_BLOCKS) g_boff[tid] = ex;
}

__global__ __launch_bounds__(256) void scan_p3(int E) {
    int i = blockIdx.x * 256 + threadIdx.x;
    int v = (i < NN) ? g_cursor[i] : 0;
    int ex = block_exscan(v, threadIdx.x) + g_boff[blockIdx.x];
    if (i < NN) {
        g_rowptr[i] = ex;
        g_cursor[i] = ex;
        float ds = rsqrtf(g_deg[i] + 1.0f);
        g_dis[i] = ds;
        g_self[i] = ds * ds;
    }
    if (i == 0) g_rowptr[NN] = E;
}

__global__ void scatter_kernel(const int* __restrict__ ei, const float* __restrict__ ew, int E) {
    int e = blockIdx.x * blockDim.x + threadIdx.x;
    if (e < E) {
        int s = ei[e];
        int d = ei[E + e];
        int pos = atomicAdd(&g_cursor[d], 1);
        g_esrc[pos] = s;
        g_ewn[pos] = g_dis[s] * ew[e] * g_dis[d];
    }
}

// ---------------- standalone SpMM for x (NCH=3, fp16 feat, fp32 accum) ----------------
__global__ void spmm_x_kernel() {
    const int C = 192;
    int gw = (blockIdx.x * blockDim.x + threadIdx.x) >> 5;
    if (gw >= NN) return;
    int lane = threadIdx.x & 31;
    int half = lane >> 4;
    int cl = lane & 15;
    int n = gw;
    int rs = g_rowptr[n], re = g_rowptr[n + 1];
    int cnt = re - rs;
    int c0 = (cnt + 1) >> 1;
    int start = rs + half * c0;
    int myCnt = half ? (cnt - c0) : c0;

    float4 acc[3];
    #pragma unroll
    for (int c = 0; c < 3; c++) acc[c] = make_float4(0.f, 0.f, 0.f, 0.f);

    if (half == 0) {
        float sn = g_self[n];
        const __half* fr = g_xh + (size_t)n * C;
        #pragma unroll
        for (int c = 0; c < 3; c++) {
            uint2 v = *(const uint2*)&fr[c * 64 + cl * 4];
            float2 f0 = __half22float2(*reinterpret_cast<__half2*>(&v.x));
            float2 f1 = __half22float2(*reinterpret_cast<__half2*>(&v.y));
            acc[c].x = sn * f0.x; acc[c].y = sn * f0.y;
            acc[c].z = sn * f1.x; acc[c].w = sn * f1.y;
        }
    }

    int iters = (c0 + 15) >> 4;
    for (int it = 0; it < iters; it++) {
        int base = it * 16;
        int s = 0; float w = 0.f;
        if (base + cl < myCnt) {
            int e = start + base + cl;
            s = g_esrc[e];
            w = g_ewn[e];
        }
        #pragma unroll
        for (int j = 0; j < 16; j++) {
            int sj = __shfl_sync(0xffffffffu, s, (lane & 16) + j);
            float wj = __shfl_sync(0xffffffffu, w, (lane & 16) + j);
            if (wj != 0.f) {
                const __half* fr = g_xh + (size_t)sj * C;
                #pragma unroll
                for (int c = 0; c < 3; c++) {
                    uint2 v = *(const uint2*)&fr[c * 64 + cl * 4];
                    float2 f0 = __half22float2(*reinterpret_cast<__half2*>(&v.x));
                    float2 f1 = __half22float2(*reinterpret_cast<__half2*>(&v.y));
                    acc[c].x += wj * f0.x; acc[c].y += wj * f0.y;
                    acc[c].z += wj * f1.x; acc[c].w += wj * f1.y;
                }
            }
        }
    }
    #pragma unroll
    for (int c = 0; c < 3; c++) {
        acc[c].x += __shfl_xor_sync(0xffffffffu, acc[c].x, 16);
        acc[c].y += __shfl_xor_sync(0xffffffffu, acc[c].y, 16);
        acc[c].z += __shfl_xor_sync(0xffffffffu, acc[c].z, 16);
        acc[c].w += __shfl_xor_sync(0xffffffffu, acc[c].w, 16);
    }
    if (half == 0) {
        #pragma unroll
        for (int c = 0; c < 3; c++)
            *(float4*)&g_AX[(size_t)n * C + c * 64 + cl * 4] = acc[c];
    }
}

// ---------------- fused gather: aggregate 64-col fp16 table rows into As h-part ----------------
// warp w handles nodes w*8 .. w*8+7 of the tile; As layout [k][68], k = FF + col
__device__ __forceinline__ void gather_to_As(const __half* __restrict__ feat,
                                             float* __restrict__ As, int block_row) {
    int wid = threadIdx.x >> 5;
    int lane = threadIdx.x & 31;
    int half = lane >> 4;
    int cl = lane & 15;
    #pragma unroll 1
    for (int rr = 0; rr < 8; rr++) {
        int r = wid * 8 + rr;
        int n = block_row + r;
        if (n >= NN) break;   // uniform across warp
        int rs = g_rowptr[n], re = g_rowptr[n + 1];
        int cnt = re - rs;
        int c0 = (cnt + 1) >> 1;
        int start = rs + half * c0;
        int myCnt = half ? (cnt - c0) : c0;

        float4 acc = make_float4(0.f, 0.f, 0.f, 0.f);
        if (half == 0) {
            float sn = g_self[n];
            uint2 v = *(const uint2*)&feat[(size_t)n * HH + cl * 4];
            float2 f0 = __half22float2(*reinterpret_cast<__half2*>(&v.x));
            float2 f1 = __half22float2(*reinterpret_cast<__half2*>(&v.y));
            acc.x = sn * f0.x; acc.y = sn * f0.y;
            acc.z = sn * f1.x; acc.w = sn * f1.y;
        }

        int iters = (c0 + 15) >> 4;
        for (int it = 0; it < iters; it++) {
            int base = it * 16;
            int s = 0; float w = 0.f;
            if (base + cl < myCnt) {
                int e = start + base + cl;
                s = g_esrc[e];
                w = g_ewn[e];
            }
            #pragma unroll
            for (int j = 0; j < 16; j++) {
                int sj = __shfl_sync(0xffffffffu, s, (lane & 16) + j);
                float wj = __shfl_sync(0xffffffffu, w, (lane & 16) + j);
                if (wj != 0.f) {
                    uint2 v = *(const uint2*)&feat[(size_t)sj * HH + cl * 4];
                    float2 f0 = __half22float2(*reinterpret_cast<__half2*>(&v.x));
                    float2 f1 = __half22float2(*reinterpret_cast<__half2*>(&v.y));
                    acc.x += wj * f0.x; acc.y += wj * f0.y;
                    acc.z += wj * f1.x; acc.w += wj * f1.y;
                }
            }
        }
        acc.x += __shfl_xor_sync(0xffffffffu, acc.x, 16);
        acc.y += __shfl_xor_sync(0xffffffffu, acc.y, 16);
        acc.z += __shfl_xor_sync(0xffffffffu, acc.z, 16);
        acc.w += __shfl_xor_sync(0xffffffffu, acc.w, 16);
        if (half == 0) {
            int kb = FF + cl * 4;
            As[(kb + 0) * 68 + r] = acc.x;
            As[(kb + 1) * 68 + r] = acc.y;
            As[(kb + 2) * 68 + r] = acc.z;
            As[(kb + 3) * 68 + r] = acc.w;
        }
    }
}

// ---------------- fused GEMM z/r: [AX_t | A@h] (N x 80) @ [Wz | Wr] (80 x 128) ----------------
#define ZR_SMEM ((KK * 68 + KK * 128) * 4)
__global__ __launch_bounds__(256, 2) void gemm_zr_fused(
    int t, const float* __restrict__ Wz, const float* __restrict__ bz,
    const float* __restrict__ Wr, const float* __restrict__ br_) {
    extern __shared__ float sm[];
    float* As = sm;            // [80][68]
    float* Bs = sm + KK * 68;  // [80][128]
    const float* hprev = (t == 0) ? g_h0 : (g_hs + (size_t)(t - 1) * NN * HH);
    int tid = threadIdx.x;

    for (int i = tid; i < KK * 128; i += 256) {
        int k = i >> 7, j = i & 127;
        Bs[i] = (j < HH) ? Wz[k * HH + j] : Wr[k * HH + (j - HH)];
    }

    int tc = tid & 15, tr = tid >> 4;

    for (int tile = blockIdx.x; tile < NTILES; tile += gridDim.x) {
        int block_row = tile * 64;
        __syncthreads();   // As free to overwrite; also orders Bs on first iter

        // x-part: k in [0,16)
        for (int i = tid; i < 64 * FF; i += 256) {
            int r = i >> 4, k = i & 15;
            int row = block_row + r;
            As[k * 68 + r] = (row < NN) ? g_AX[(size_t)row * FT + k * TT + t] : 0.f;
        }
        // h-part: k in [16,80)
        if (t > 0) {
            gather_to_As(g_hh, As, block_row);
        } else {
            for (int i = tid; i < 64 * HH; i += 256) {
                int r = i >> 6, k = i & 63;
                As[(FF + k) * 68 + r] = 0.f;
            }
        }
        __syncthreads();

        float acc[4][8];
        #pragma unroll
        for (int rr = 0; rr < 4; rr++)
            #pragma unroll
            for (int cc = 0; cc < 8; cc++) acc[rr][cc] = 0.f;

        #pragma unroll 8
        for (int k = 0; k < KK; k++) {
            float4 a = *(float4*)&As[k * 68 + tr * 4];
            float4 b0 = *(float4*)&Bs[k * 128 + tc * 8];
            float4 b1 = *(float4*)&Bs[k * 128 + tc * 8 + 4];
            float av[4] = {a.x, a.y, a.z, a.w};
            float bv[8] = {b0.x, b0.y, b0.z, b0.w, b1.x, b1.y, b1.z, b1.w};
            #pragma unroll
            for (int rr = 0; rr < 4; rr++)
                #pragma unroll
                for (int cc = 0; cc < 8; cc++)
                    acc[rr][cc] += av[rr] * bv[cc];
        }

        #pragma unroll
        for (int rr = 0; rr < 4; rr++) {
            int row = block_row + tr * 4 + rr;
            if (row < NN) {
                #pragma unroll
                for (int cc = 0; cc < 8; cc++) {
                    int j = tc * 8 + cc;
                    float v = acc[rr][cc];
                    if (j < HH) {
                        g_Z[(size_t)row * HH + j] = sigm(v + bz[j]);
                    } else {
                        int jj = j - HH;
                        float rv = sigm(v + br_[jj]);
                        g_RHh[(size_t)row * HH + jj] =
                            __float2half_rn(rv * hprev[(size_t)row * HH + jj]);
                    }
                }
            }
        }
    }
}

// ---------------- fused GEMM h: [AX_t | A@(r*h)] @ Wh; GRU update -> hs[t], hh ----------------
__global__ __launch_bounds__(256, 3) void gemm_h_fused(
    int t, const float* __restrict__ Wh, const float* __restrict__ bh) {
    __shared__ float As[KK * 68];
    __shared__ float Bs[KK * HH];
    const float* hprev = (t == 0) ? g_h0 : (g_hs + (size_t)(t - 1) * NN * HH);
    float* hout = g_hs + (size_t)t * NN * HH;
    int tid = threadIdx.x;

    for (int i = tid; i < KK * HH; i += 256) Bs[i] = Wh[i];

    int tc = tid & 15, tr = tid >> 4;

    for (int tile = blockIdx.x; tile < NTILES; tile += gridDim.x) {
        int block_row = tile * 64;
        __syncthreads();

        for (int i = tid; i < 64 * FF; i += 256) {
            int r = i >> 4, k = i & 15;
            int row = block_row + r;
            As[k * 68 + r] = (row < NN) ? g_AX[(size_t)row * FT + k * TT + t] : 0.f;
        }
        if (t > 0) {
            gather_to_As(g_RHh, As, block_row);
        } else {
            for (int i = tid; i < 64 * HH; i += 256) {
                int r = i >> 6, k = i & 63;
                As[(FF + k) * 68 + r] = 0.f;
            }
        }
        __syncthreads();

        float acc[4][4];
        #pragma unroll
        for (int rr = 0; rr < 4; rr++)
            #pragma unroll
            for (int cc = 0; cc < 4; cc++) acc[rr][cc] = 0.f;

        #pragma unroll 8
        for (int k = 0; k < KK; k++) {
            float4 a = *(float4*)&As[k * 68 + tr * 4];
            float4 b = *(float4*)&Bs[k * HH + tc * 4];
            float av[4] = {a.x, a.y, a.z, a.w};
            float bv[4] = {b.x, b.y, b.z, b.w};
            #pragma unroll
            for (int rr = 0; rr < 4; rr++)
                #pragma unroll
                for (int cc = 0; cc < 4; cc++)
                    acc[rr][cc] += av[rr] * bv[cc];
        }

        #pragma unroll
        for (int rr = 0; rr < 4; rr++) {
            int row = block_row + tr * 4 + rr;
            if (row < NN) {
                #pragma unroll
                for (int cc = 0; cc < 4; cc++) {
                    int j = tc * 4 + cc;
                    float hc = tanh_fast(acc[rr][cc] + bh[j]);
                    float z = g_Z[(size_t)row * HH + j];
                    float hp = hprev[(size_t)row * HH + j];
                    float hn = z * hp + (1.f - z) * hc;
                    hout[(size_t)row * HH + j] = hn;
                    g_hh[(size_t)row * HH + j] = __float2half_rn(hn);
                }
            }
        }
    }
}

// ---------------- attention score ----------------
__global__ __launch_bounds__(256) void attn_score_kernel(
    const float* __restrict__ Wa, const float* __restrict__ ba, const float* __restrict__ cv) {
    __shared__ float As[HH * 68];
    __shared__ float Bs[HH * HH];
    __shared__ float ba_s[HH], cv_s[HH];
    const int TN = TT * NN;
    int tid = threadIdx.x;
    int block_row = blockIdx.x * 64;

    for (int i = tid; i < 64 * HH; i += 256) {
        int r = i >> 6, k = i & 63;
        int row = block_row + r;
        As[k * 68 + r] = (row < TN) ? g_hs[(size_t)row * HH + k] : 0.f;
    }
    for (int i = tid; i < HH * HH; i += 256) Bs[i] = Wa[i];
    if (tid < HH) { ba_s[tid] = ba[tid]; cv_s[tid] = cv[tid]; }
    __syncthreads();

    int tc = tid & 15, tr = tid >> 4;
    float acc[4][4];
    #pragma unroll
    for (int rr = 0; rr < 4; rr++)
        #pragma unroll
        for (int cc = 0; cc < 4; cc++) acc[rr][cc] = 0.f;

    #pragma unroll 8
    for (int k = 0; k < HH; k++) {
        float4 a = *(float4*)&As[k * 68 + tr * 4];
        float4 b = *(float4*)&Bs[k * HH + tc * 4];
        float av[4] = {a.x, a.y, a.z, a.w};
        float bv[4] = {b.x, b.y, b.z, b.w};
        #pragma unroll
        for (int rr = 0; rr < 4; rr++)
            #pragma unroll
            for (int cc = 0; cc < 4; cc++)
                acc[rr][cc] += av[rr] * bv[cc];
    }

    #pragma unroll
    for (int rr = 0; rr < 4; rr++) {
        float p = 0.f;
        #pragma unroll
        for (int cc = 0; cc < 4; cc++) {
            int j = tc * 4 + cc;
            p += tanh_fast(acc[rr][cc] + ba_s[j]) * cv_s[j];
        }
        #pragma unroll
        for (int off = 1; off < 16; off <<= 1)
            p += __shfl_xor_sync(0xffffffffu, p, off);
        int row = block_row + tr * 4 + rr;
        if (tc == 0 && row < TN) {
            int t = row / NN;
            int n = row % NN;
            g_align[(size_t)n * TT + t] = p;
        }
    }
}

// ---------------- softmax over T + context + FC ----------------
__global__ __launch_bounds__(256) void attn_out_kernel(
    const float* __restrict__ Wfc, const float* __restrict__ bfc, float* __restrict__ out) {
    __shared__ float wf_s[HH];
    __shared__ float red[4][2];
    int tid = threadIdx.x;
    int g = tid >> 6, j = tid & 63;
    int n = blockIdx.x * 4 + g;
    if (tid < HH) wf_s[tid] = Wfc[tid];
    __syncthreads();
    if (n >= NN) return;

    float a[TT];
    float m = -1e30f;
    #pragma unroll
    for (int t = 0; t < TT; t++) { a[t] = g_align[(size_t)n * TT + t]; m = fmaxf(m, a[t]); }
    float se = 0.f;
    #pragma unroll
    for (int t = 0; t < TT; t++) { a[t] = __expf(a[t] - m); se += a[t]; }
    float inv = 1.f / se;
    float ctx = 0.f;
    #pragma unroll
    for (int t = 0; t < TT; t++)
        ctx += a[t] * g_hs[(size_t)t * NN * HH + (size_t)n * HH + j];
    ctx *= inv;

    float p = ctx * wf_s[j];
    #pragma unroll
    for (int off = 16; off > 0; off >>= 1)
        p += __shfl_xor_sync(0xffffffffu, p, off);
    int lane = tid & 31;
    if (lane == 0) red[g][j >> 5] = p;
    __syncthreads();
    if (j == 0) out[n] = red[g][0] + red[g][1] + bfc[0];
}

// ---------------- launch ----------------
extern "C" void kernel_launch(void* const* d_in, const int* in_sizes, int n_in,
                              void* d_out, int out_size) {
    const float* x   = (const float*)d_in[0];
    const int*   ei  = (const int*)d_in[1];
    const float* ew  = (const float*)d_in[2];
    const float* Wz  = (const float*)d_in[3];
    const float* bz  = (const float*)d_in[4];
    const float* Wr  = (const float*)d_in[5];
    const float* br_ = (const float*)d_in[6];
    const float* Wh  = (const float*)d_in[7];
    const float* bh  = (const float*)d_in[8];
    const float* Wa  = (const float*)d_in[9];
    const float* ba  = (const float*)d_in[10];
    const float* cv  = (const float*)d_in[11];
    const float* Wfc = (const float*)d_in[12];
    const float* bfc = (const float*)d_in[13];
    float* out = (float*)d_out;
    int E = in_sizes[2];

    static int attr_done = 0;
    if (!attr_done) {
        cudaFuncSetAttribute(gemm_zr_fused, cudaFuncAttributeMaxDynamicSharedMemorySize, ZR_SMEM);
        attr_done = 1;
    }

    init_kernel<<<(NN + 255) / 256, 256>>>();
    tohalf_kernel<<<(NN * FT / 2 + 255) / 256, 256>>>(x);
    hist_kernel<<<(E + 255) / 256, 256>>>(ei, ew, E);
    scan_p1<<<SCAN_BLOCKS, 256>>>();
    scan_p2<<<1, 256>>>();
    scan_p3<<<SCAN_BLOCKS, 256>>>(E);
    scatter_kernel<<<(E + 255) / 256, 256>>>(ei, ew, E);

    spmm_x_kernel<<<(NN + 7) / 8, 256>>>();

    const int ZR_GRID = 148 * 2;   // persistent, 2 blocks/SM (smem-limited)
    const int H_GRID  = 148 * 3;   // persistent, 3 blocks/SM
    for (int t = 0; t < TT; t++) {
        gemm_zr_fused<<<ZR_GRID, 256, ZR_SMEM>>>(t, Wz, bz, Wr, br_);
        gemm_h_fused<<<H_GRID, 256>>>(t, Wh, bh);
    }

    attn_score_kernel<<<(TT * NN + 63) / 64, 256>>>(Wa, ba, cv);
    attn_out_kernel<<<(NN + 3) / 4, 256>>>(Wfc, bfc, out);
}